// round 5
// baseline (speedup 1.0000x reference)
#include <cuda_runtime.h>
#include <math.h>

// Problem constants (fixed by the reference)
#define NN 50000
#define EE 600000
#define DD 128
#define HH 4
#define INV_SCALE 0.17677669529663687f  // 1/sqrt(32)

// ---------------------------------------------------------------------------
// Scratch (device globals — no allocations allowed)
// ---------------------------------------------------------------------------
__device__ float g_Wqkv[3 * DD * DD];             // packed [384,128] weights
__device__ float g_QKV[(size_t)NN * 3 * DD];      // per node: [Q(128) K(128) V(128)]
__device__ float g_wV[NN * DD];
__device__ float g_z[NN * HH];
__device__ float g_h[NN * DD];
__device__ float g_hid_n[NN * 2 * DD];
__device__ float g_score[(size_t)EE * DD];        // proj_e, then score (in-place)
__device__ float g_hid_e[(size_t)EE * 2 * DD];

__device__ __forceinline__ float silu_fast(float x) {
    return __fdividef(x, 1.0f + __expf(-x));
}

// ---------------------------------------------------------------------------
// Pack Wq|Wk|Wv into one [384,128] matrix
// ---------------------------------------------------------------------------
__global__ void pack_qkv_weights(const float* __restrict__ Wq,
                                 const float* __restrict__ Wk,
                                 const float* __restrict__ Wv) {
    int i = blockIdx.x * blockDim.x + threadIdx.x;
    if (i >= 3 * DD * DD / 4) return;
    const int per = DD * DD / 4;
    float4 v;
    if (i < per)            v = ((const float4*)Wq)[i];
    else if (i < 2 * per)   v = ((const float4*)Wk)[i - per];
    else                    v = ((const float4*)Wv)[i - 2 * per];
    ((float4*)g_Wqkv)[i] = v;
}

// ---------------------------------------------------------------------------
// SGEMM:  C[m,n] = act( sum_k A[m,k] * W[n,k] )   (C = A @ W^T)
//   BM=BN=128, BK=8, 256 threads, 8x8 per thread.
//   Inner loop uses packed fma.rn.f32x2 (full-rate fp32 path on sm_103a;
//   3-reg FFMA is half-rate). Bit-exact fp32.
//   Global->register prefetch double buffering hides LDG latency.
//   Requires: N % 128 == 0, K % 8 == 0.
// ---------------------------------------------------------------------------
template <int ACT>
__global__ void __launch_bounds__(256, 2)
sgemm_nt(const float* __restrict__ A, const float* __restrict__ W,
         float* __restrict__ C, int M, int N, int K) {
    constexpr int BM = 128, BN = 128, BK = 8;
    __shared__ float As[BK][BM];
    __shared__ float Bs[BK][BN];

    const int t  = threadIdx.x;
    const int m0 = blockIdx.x * BM;
    const int n0 = blockIdx.y * BN;

    // load mapping: 128 rows x 8 cols = 1024 floats = 256 x float4
    const int lr = t >> 1;          // 0..127
    const int lc = (t & 1) * 4;     // 0 or 4

    // compute mapping: 16x16 thread grid, 8x8 per thread
    const int rm = (t >> 4) * 8;    // 0..120
    const int rn = (t & 15) * 8;    // 0..120

    const int  gm      = m0 + lr;
    const bool a_valid = (gm < M);
    const float* a_src = A + (size_t)gm * K + lc;          // + k0
    const float* b_src = W + (size_t)(n0 + lr) * K + lc;   // + k0

    // accumulators as f32x2 pairs: acc2[i][j] = {C[i][2j], C[i][2j+1]}
    unsigned long long acc2[8][4];
    #pragma unroll
    for (int i = 0; i < 8; i++)
        #pragma unroll
        for (int j = 0; j < 4; j++) acc2[i][j] = 0ull;

    // prologue: fetch tile 0
    float4 a_nxt = make_float4(0.f, 0.f, 0.f, 0.f);
    if (a_valid) a_nxt = *(const float4*)(a_src);
    float4 b_nxt = *(const float4*)(b_src);

    for (int k0 = 0; k0 < K; k0 += BK) {
        As[lc + 0][lr] = a_nxt.x; As[lc + 1][lr] = a_nxt.y;
        As[lc + 2][lr] = a_nxt.z; As[lc + 3][lr] = a_nxt.w;
        Bs[lc + 0][lr] = b_nxt.x; Bs[lc + 1][lr] = b_nxt.y;
        Bs[lc + 2][lr] = b_nxt.z; Bs[lc + 3][lr] = b_nxt.w;
        __syncthreads();

        const int kn = k0 + BK;
        if (kn < K) {
            a_nxt = make_float4(0.f, 0.f, 0.f, 0.f);
            if (a_valid) a_nxt = *(const float4*)(a_src + kn);
            b_nxt = *(const float4*)(b_src + kn);
        }

        #pragma unroll
        for (int k = 0; k < BK; k++) {
            float ra[8];
            *(float4*)&ra[0] = *(const float4*)&As[k][rm];
            *(float4*)&ra[4] = *(const float4*)&As[k][rm + 4];

            // B as four 64-bit f32 pairs (8-byte aligned: rn % 8 == 0)
            unsigned long long rb2[4];
            rb2[0] = *(const unsigned long long*)&Bs[k][rn + 0];
            rb2[1] = *(const unsigned long long*)&Bs[k][rn + 2];
            rb2[2] = *(const unsigned long long*)&Bs[k][rn + 4];
            rb2[3] = *(const unsigned long long*)&Bs[k][rn + 6];

            unsigned long long aa[8];
            #pragma unroll
            for (int i = 0; i < 8; i++)
                asm("mov.b64 %0, {%1, %1};" : "=l"(aa[i]) : "f"(ra[i]));

            #pragma unroll
            for (int i = 0; i < 8; i++)
                #pragma unroll
                for (int j = 0; j < 4; j++)
                    asm("fma.rn.f32x2 %0, %1, %2, %0;"
                        : "+l"(acc2[i][j]) : "l"(aa[i]), "l"(rb2[j]));
        }
        __syncthreads();
    }

    #pragma unroll
    for (int i = 0; i < 8; i++) {
        int gmo = m0 + rm + i;
        if (gmo >= M) continue;
        float acc[8];
        #pragma unroll
        for (int j = 0; j < 4; j++)
            asm("mov.b64 {%0, %1}, %2;"
                : "=f"(acc[2 * j]), "=f"(acc[2 * j + 1]) : "l"(acc2[i][j]));
        float* crow = C + (size_t)gmo * N + n0 + rn;
        float4 o0, o1;
        if (ACT == 1) {
            o0 = make_float4(silu_fast(acc[0]), silu_fast(acc[1]),
                             silu_fast(acc[2]), silu_fast(acc[3]));
            o1 = make_float4(silu_fast(acc[4]), silu_fast(acc[5]),
                             silu_fast(acc[6]), silu_fast(acc[7]));
        } else {
            o0 = make_float4(acc[0], acc[1], acc[2], acc[3]);
            o1 = make_float4(acc[4], acc[5], acc[6], acc[7]);
        }
        *(float4*)(crow)     = o0;
        *(float4*)(crow + 4) = o1;
    }
}

// ---------------------------------------------------------------------------
// Per-edge attention: one WARP per edge, lane handles 4 contiguous floats.
//   QKV packed per node: row stride 384 floats [Q | K | V]
// ---------------------------------------------------------------------------
__global__ void __launch_bounds__(256)
edge_attn_kernel(const int* __restrict__ src, const int* __restrict__ dst,
                 float* __restrict__ score) {
    const int warp = threadIdx.x >> 5;
    const int lane = threadIdx.x & 31;
    const int e = blockIdx.x * 8 + warp;
    if (e >= EE) return;

    const int sn = __ldg(src + e);
    const int dn = __ldg(dst + e);
    const int base = lane * 4;              // 0..124; head = lane>>3

    const float* srow = g_QKV + (size_t)sn * (3 * DD);
    const float* drow = g_QKV + (size_t)dn * (3 * DD);

    float4 q4 = *(const float4*)(drow + base);              // Q[dst]
    float4 k4 = *(const float4*)(srow + DD + base);         // K[src]
    float4 p4 = *(const float4*)(score + (size_t)e * DD + base);

    float4 sc;
    sc.x = fminf(5.f, fmaxf(-5.f, k4.x * q4.x * INV_SCALE)) * p4.x;
    sc.y = fminf(5.f, fmaxf(-5.f, k4.y * q4.y * INV_SCALE)) * p4.y;
    sc.z = fminf(5.f, fmaxf(-5.f, k4.z * q4.z * INV_SCALE)) * p4.z;
    sc.w = fminf(5.f, fmaxf(-5.f, k4.w * q4.w * INV_SCALE)) * p4.w;
    *(float4*)(score + (size_t)e * DD + base) = sc;

    // reduce 32 values per head: 4 in-thread + butterfly over the 8-lane group
    float sum = (sc.x + sc.y) + (sc.z + sc.w);
    #pragma unroll
    for (int off = 4; off > 0; off >>= 1)
        sum += __shfl_xor_sync(0xffffffffu, sum, off);

    float s = __expf(fminf(5.f, fmaxf(-5.f, sum)));

    float4 v4 = *(const float4*)(srow + 2 * DD + base);     // V[src]
    float4* wv = (float4*)(g_wV + (size_t)dn * DD + base);
    atomicAdd(wv, make_float4(v4.x * s, v4.y * s, v4.z * s, v4.w * s));
    if ((lane & 7) == 0) atomicAdd(&g_z[dn * HH + (lane >> 3)], s);
}

// ---------------------------------------------------------------------------
// h = wV / (z + 1e-6), float4-wide
// ---------------------------------------------------------------------------
__global__ void divide_kernel() {
    int idx = blockIdx.x * blockDim.x + threadIdx.x;   // one float4 per thread
    if (idx >= NN * DD / 4) return;
    int fbase = idx * 4;
    int n = fbase >> 7;
    int head = (fbase & 127) >> 5;
    float inv = __fdividef(1.0f, g_z[n * HH + head] + 1e-6f);
    float4 w = *(const float4*)(g_wV + fbase);
    w.x *= inv; w.y *= inv; w.z *= inv; w.w *= inv;
    *(float4*)(g_h + fbase) = w;
}

// ---------------------------------------------------------------------------
// kernel_launch
// inputs: 0 node_feats 1 edge_feats 2 src 3 dst 4 Wq 5 Wk 6 Wv 7 We
//         8 Wn1 9 Wn2 10 We1 11 We2
// output: [node_out (N*128) | edge_out (E*128)] fp32
// ---------------------------------------------------------------------------
extern "C" void kernel_launch(void* const* d_in, const int* in_sizes, int n_in,
                              void* d_out, int out_size) {
    const float* node_feats = (const float*)d_in[0];
    const float* edge_feats = (const float*)d_in[1];
    const int*   src        = (const int*)d_in[2];
    const int*   dst        = (const int*)d_in[3];
    const float* Wq  = (const float*)d_in[4];
    const float* Wk  = (const float*)d_in[5];
    const float* Wv  = (const float*)d_in[6];
    const float* We  = (const float*)d_in[7];
    const float* Wn1 = (const float*)d_in[8];
    const float* Wn2 = (const float*)d_in[9];
    const float* We1 = (const float*)d_in[10];
    const float* We2 = (const float*)d_in[11];

    float* node_out = (float*)d_out;
    float* edge_out = (float*)d_out + (size_t)NN * DD;

    float *pWqkv, *pQKV, *pWV, *pZ, *pH, *pHidN, *pScore, *pHidE;
    cudaGetSymbolAddress((void**)&pWqkv,  g_Wqkv);
    cudaGetSymbolAddress((void**)&pQKV,   g_QKV);
    cudaGetSymbolAddress((void**)&pWV,    g_wV);
    cudaGetSymbolAddress((void**)&pZ,     g_z);
    cudaGetSymbolAddress((void**)&pH,     g_h);
    cudaGetSymbolAddress((void**)&pHidN,  g_hid_n);
    cudaGetSymbolAddress((void**)&pScore, g_score);
    cudaGetSymbolAddress((void**)&pHidE,  g_hid_e);

    // 0) zero accumulators + pack weights (every replay; all capturable)
    cudaMemsetAsync(pWV, 0, (size_t)NN * DD * sizeof(float));
    cudaMemsetAsync(pZ,  0, (size_t)NN * HH * sizeof(float));
    pack_qkv_weights<<<(3 * DD * DD / 4 + 255) / 256, 256>>>(Wq, Wk, Wv);

    // 1) QKV projection in one GEMM: [N,128] x [384,128]^T -> [N,384]
    {
        dim3 grid((NN + 127) / 128, (3 * DD) / 128);
        sgemm_nt<0><<<grid, 256>>>(node_feats, pWqkv, pQKV, NN, 3 * DD, DD);
    }

    // 2) proj_e = edge_feats @ We^T : [E,128]
    {
        dim3 grid((EE + 127) / 128, DD / 128);
        sgemm_nt<0><<<grid, 256>>>(edge_feats, We, pScore, EE, DD, DD);
    }

    // 3) per-edge attention + scatter (8 warps/block, 1 edge/warp)
    edge_attn_kernel<<<(EE + 7) / 8, 256>>>(src, dst, pScore);

    // 4) h = wV / (z + eps)
    divide_kernel<<<(NN * DD / 4 + 255) / 256, 256>>>();

    // 5) node MLP: silu(h @ Wn1^T) @ Wn2^T
    {
        dim3 g1((NN + 127) / 128, (2 * DD) / 128);
        sgemm_nt<1><<<g1, 256>>>(pH, Wn1, pHidN, NN, 2 * DD, DD);
        dim3 g2((NN + 127) / 128, DD / 128);
        sgemm_nt<0><<<g2, 256>>>(pHidN, Wn2, node_out, NN, DD, 2 * DD);
    }

    // 6) edge MLP: silu(score @ We1^T) @ We2^T
    {
        dim3 g1((EE + 127) / 128, (2 * DD) / 128);
        sgemm_nt<1><<<g1, 256>>>(pScore, We1, pHidE, EE, 2 * DD, DD);
        dim3 g2((EE + 127) / 128, DD / 128);
        sgemm_nt<0><<<g2, 256>>>(pHidE, We2, edge_out, EE, DD, 2 * DD);
    }
}

// round 7
// speedup vs baseline: 1.5036x; 1.5036x over previous
#include <cuda_runtime.h>
#include <cuda_bf16.h>
#include <math.h>
#include <stdint.h>

// Problem constants (fixed by the reference)
#define NN 50000
#define EE 600000
#define DD 128
#define HH 4
#define INV_SCALE 0.17677669529663687f  // 1/sqrt(32)

// ---------------------------------------------------------------------------
// Scratch (device globals — no allocations allowed)
// ---------------------------------------------------------------------------
__device__ float g_Wqkv[3 * DD * DD];             // packed [384,128] weights
__device__ float g_QKV[(size_t)NN * 3 * DD];      // per node: [Q(128) K(128) V(128)]
__device__ float g_wV[NN * DD];
__device__ float g_z[NN * HH];
__device__ float g_h[NN * DD];
__device__ float g_hid_n[NN * 2 * DD];
__device__ float g_score[(size_t)EE * DD];        // proj_e, then score (in-place)
__device__ float g_hid_e[(size_t)EE * 2 * DD];

__device__ __forceinline__ float silu_fast(float x) {
    return __fdividef(x, 1.0f + __expf(-x));
}

// hi/lo split helpers: x = hi + lo with hi = bf16(x)
__device__ __forceinline__ uint32_t pack_hi(float x0, float x1) {
    __nv_bfloat162 r = __floats2bfloat162_rn(x0, x1);
    return *(uint32_t*)&r;
}
__device__ __forceinline__ uint32_t pack_lo(float x0, float x1) {
    float h0 = __bfloat162float(__float2bfloat16(x0));
    float h1 = __bfloat162float(__float2bfloat16(x1));
    __nv_bfloat162 r = __floats2bfloat162_rn(x0 - h0, x1 - h1);
    return *(uint32_t*)&r;
}

// ---------------------------------------------------------------------------
// Pack Wq|Wk|Wv into one [384,128] matrix
// ---------------------------------------------------------------------------
__global__ void pack_qkv_weights(const float* __restrict__ Wq,
                                 const float* __restrict__ Wk,
                                 const float* __restrict__ Wv) {
    int i = blockIdx.x * blockDim.x + threadIdx.x;
    if (i >= 3 * DD * DD / 4) return;
    const int per = DD * DD / 4;
    float4 v;
    if (i < per)            v = ((const float4*)Wq)[i];
    else if (i < 2 * per)   v = ((const float4*)Wk)[i - per];
    else                    v = ((const float4*)Wv)[i - 2 * per];
    ((float4*)g_Wqkv)[i] = v;
}

// ---------------------------------------------------------------------------
// Split-bf16 tensor-core GEMM:  C[m,n] = act( sum_k A[m,k] * W[n,k] )
//   (C = A @ W^T).  A:[M,K] row-major, W:[N,K] row-major.
//   fp32 operands split into bf16 hi+lo at tile load; 3 MMAs per product
//   (hi*hi + hi*lo + lo*hi) accumulate in fp32 -> rel err ~1e-5.
//   BM=128, BN=64, BK=32, 256 threads (8 warps), warp tile 32x32.
//   Requires: N % 64 == 0, K % 32 == 0 (true: N in {128,256,384}, K in {128,256}).
// ---------------------------------------------------------------------------
#define MMA16816(acc, a0, a1, a2, a3, b0, b1)                               \
    asm("mma.sync.aligned.m16n8k16.row.col.f32.bf16.bf16.f32 "              \
        "{%0,%1,%2,%3}, {%4,%5,%6,%7}, {%8,%9}, {%0,%1,%2,%3};"             \
        : "+f"(acc[0]), "+f"(acc[1]), "+f"(acc[2]), "+f"(acc[3])            \
        : "r"(a0), "r"(a1), "r"(a2), "r"(a3), "r"(b0), "r"(b1))

template <int ACT>
__global__ void __launch_bounds__(256, 2)
mma_gemm_nt(const float* __restrict__ A, const float* __restrict__ W,
            float* __restrict__ C, int M, int N, int K) {
    constexpr int BM = 128, BN = 64, BK = 32;
    constexpr int LDT = 40;   // padded row stride in bf16 (conflict-free frag reads)

    __shared__ __nv_bfloat16 Ah[BM][LDT];
    __shared__ __nv_bfloat16 Al[BM][LDT];
    __shared__ __nv_bfloat16 Bh[BN][LDT];
    __shared__ __nv_bfloat16 Bl[BN][LDT];

    const int t    = threadIdx.x;
    const int lane = t & 31;
    const int warp = t >> 5;
    const int wm   = (warp >> 1) * 32;    // 0,32,64,96
    const int wn   = (warp & 1) * 32;     // 0,32
    const int g    = lane >> 2;           // 0..7
    const int tig  = lane & 3;            // 0..3

    const int m0 = blockIdx.x * BM;
    const int n0 = blockIdx.y * BN;

    // A loader mapping: thread -> (row = t>>1, kbase = (t&1)*16), 4 float4s
    const int ar = t >> 1;
    const int ak = (t & 1) * 16;
    // B loader mapping: thread -> (row = t>>2, kbase = (t&3)*8), 2 float4s
    const int br = t >> 2;
    const int bk = (t & 3) * 8;

    const int   a_gm    = m0 + ar;
    const bool  a_valid = (a_gm < M);
    const float* a_src  = A + (size_t)a_gm * K + ak;
    const float* b_src  = W + (size_t)(n0 + br) * K + bk;

    float acc[2][4][4];
    #pragma unroll
    for (int mi = 0; mi < 2; mi++)
        #pragma unroll
        for (int ni = 0; ni < 4; ni++)
            #pragma unroll
            for (int r = 0; r < 4; r++) acc[mi][ni][r] = 0.f;

    for (int k0 = 0; k0 < K; k0 += BK) {
        // ---- load + split A tile (packed 32-bit smem stores) ----
        #pragma unroll
        for (int i = 0; i < 4; i++) {
            float4 v = make_float4(0.f, 0.f, 0.f, 0.f);
            if (a_valid) v = *(const float4*)(a_src + k0 + i * 4);
            int kk = ak + i * 4;
            *(uint32_t*)&Ah[ar][kk + 0] = pack_hi(v.x, v.y);
            *(uint32_t*)&Ah[ar][kk + 2] = pack_hi(v.z, v.w);
            *(uint32_t*)&Al[ar][kk + 0] = pack_lo(v.x, v.y);
            *(uint32_t*)&Al[ar][kk + 2] = pack_lo(v.z, v.w);
        }
        // ---- load + split B tile ----
        #pragma unroll
        for (int i = 0; i < 2; i++) {
            float4 v = *(const float4*)(b_src + k0 + i * 4);
            int kk = bk + i * 4;
            *(uint32_t*)&Bh[br][kk + 0] = pack_hi(v.x, v.y);
            *(uint32_t*)&Bh[br][kk + 2] = pack_hi(v.z, v.w);
            *(uint32_t*)&Bl[br][kk + 0] = pack_lo(v.x, v.y);
            *(uint32_t*)&Bl[br][kk + 2] = pack_lo(v.z, v.w);
        }
        __syncthreads();

        #pragma unroll
        for (int ka = 0; ka < 2; ka++) {
            const int kb = ka * 16;
            // A fragments (hi + lo) for both m16 tiles
            uint32_t fah[2][4], fal[2][4];
            #pragma unroll
            for (int mi = 0; mi < 2; mi++) {
                int r0 = wm + mi * 16 + g;
                int c0 = kb + tig * 2;
                fah[mi][0] = *(const uint32_t*)&Ah[r0][c0];
                fah[mi][1] = *(const uint32_t*)&Ah[r0 + 8][c0];
                fah[mi][2] = *(const uint32_t*)&Ah[r0][c0 + 8];
                fah[mi][3] = *(const uint32_t*)&Ah[r0 + 8][c0 + 8];
                fal[mi][0] = *(const uint32_t*)&Al[r0][c0];
                fal[mi][1] = *(const uint32_t*)&Al[r0 + 8][c0];
                fal[mi][2] = *(const uint32_t*)&Al[r0][c0 + 8];
                fal[mi][3] = *(const uint32_t*)&Al[r0 + 8][c0 + 8];
            }
            #pragma unroll
            for (int ni = 0; ni < 4; ni++) {
                int nrow = wn + ni * 8 + g;
                int c0 = kb + tig * 2;
                uint32_t bh0 = *(const uint32_t*)&Bh[nrow][c0];
                uint32_t bh1 = *(const uint32_t*)&Bh[nrow][c0 + 8];
                uint32_t bl0 = *(const uint32_t*)&Bl[nrow][c0];
                uint32_t bl1 = *(const uint32_t*)&Bl[nrow][c0 + 8];
                #pragma unroll
                for (int mi = 0; mi < 2; mi++) {
                    MMA16816(acc[mi][ni], fah[mi][0], fah[mi][1], fah[mi][2], fah[mi][3], bh0, bh1);
                    MMA16816(acc[mi][ni], fah[mi][0], fah[mi][1], fah[mi][2], fah[mi][3], bl0, bl1);
                    MMA16816(acc[mi][ni], fal[mi][0], fal[mi][1], fal[mi][2], fal[mi][3], bh0, bh1);
                }
            }
        }
        __syncthreads();
    }

    // ---- epilogue ----
    #pragma unroll
    for (int mi = 0; mi < 2; mi++) {
        #pragma unroll
        for (int ni = 0; ni < 4; ni++) {
            int gm0 = m0 + wm + mi * 16 + g;
            int col = n0 + wn + ni * 8 + tig * 2;
            float d0 = acc[mi][ni][0], d1 = acc[mi][ni][1];
            float d2 = acc[mi][ni][2], d3 = acc[mi][ni][3];
            if (ACT == 1) {
                d0 = silu_fast(d0); d1 = silu_fast(d1);
                d2 = silu_fast(d2); d3 = silu_fast(d3);
            }
            if (gm0 < M)
                *(float2*)(C + (size_t)gm0 * N + col) = make_float2(d0, d1);
            if (gm0 + 8 < M)
                *(float2*)(C + (size_t)(gm0 + 8) * N + col) = make_float2(d2, d3);
        }
    }
}

// ---------------------------------------------------------------------------
// Per-edge attention: one WARP per edge, lane handles 4 contiguous floats.
//   QKV packed per node: row stride 384 floats [Q | K | V]
// ---------------------------------------------------------------------------
__global__ void __launch_bounds__(256)
edge_attn_kernel(const int* __restrict__ src, const int* __restrict__ dst,
                 float* __restrict__ score) {
    const int warp = threadIdx.x >> 5;
    const int lane = threadIdx.x & 31;
    const int e = blockIdx.x * 8 + warp;
    if (e >= EE) return;

    const int sn = __ldg(src + e);
    const int dn = __ldg(dst + e);
    const int base = lane * 4;              // 0..124; head = lane>>3

    const float* srow = g_QKV + (size_t)sn * (3 * DD);
    const float* drow = g_QKV + (size_t)dn * (3 * DD);

    float4 q4 = *(const float4*)(drow + base);              // Q[dst]
    float4 k4 = *(const float4*)(srow + DD + base);         // K[src]
    float4 p4 = *(const float4*)(score + (size_t)e * DD + base);

    float4 sc;
    sc.x = fminf(5.f, fmaxf(-5.f, k4.x * q4.x * INV_SCALE)) * p4.x;
    sc.y = fminf(5.f, fmaxf(-5.f, k4.y * q4.y * INV_SCALE)) * p4.y;
    sc.z = fminf(5.f, fmaxf(-5.f, k4.z * q4.z * INV_SCALE)) * p4.z;
    sc.w = fminf(5.f, fmaxf(-5.f, k4.w * q4.w * INV_SCALE)) * p4.w;
    *(float4*)(score + (size_t)e * DD + base) = sc;

    // reduce 32 values per head: 4 in-thread + butterfly over the 8-lane group
    float sum = (sc.x + sc.y) + (sc.z + sc.w);
    #pragma unroll
    for (int off = 4; off > 0; off >>= 1)
        sum += __shfl_xor_sync(0xffffffffu, sum, off);

    float s = __expf(fminf(5.f, fmaxf(-5.f, sum)));

    float4 v4 = *(const float4*)(srow + 2 * DD + base);     // V[src]
    float4* wv = (float4*)(g_wV + (size_t)dn * DD + base);
    atomicAdd(wv, make_float4(v4.x * s, v4.y * s, v4.z * s, v4.w * s));
    if ((lane & 7) == 0) atomicAdd(&g_z[dn * HH + (lane >> 3)], s);
}

// ---------------------------------------------------------------------------
// h = wV / (z + 1e-6), float4-wide
// ---------------------------------------------------------------------------
__global__ void divide_kernel() {
    int idx = blockIdx.x * blockDim.x + threadIdx.x;   // one float4 per thread
    if (idx >= NN * DD / 4) return;
    int fbase = idx * 4;
    int n = fbase >> 7;
    int head = (fbase & 127) >> 5;
    float inv = __fdividef(1.0f, g_z[n * HH + head] + 1e-6f);
    float4 w = *(const float4*)(g_wV + fbase);
    w.x *= inv; w.y *= inv; w.z *= inv; w.w *= inv;
    *(float4*)(g_h + fbase) = w;
}

// ---------------------------------------------------------------------------
// kernel_launch
// inputs: 0 node_feats 1 edge_feats 2 src 3 dst 4 Wq 5 Wk 6 Wv 7 We
//         8 Wn1 9 Wn2 10 We1 11 We2
// output: [node_out (N*128) | edge_out (E*128)] fp32
// ---------------------------------------------------------------------------
extern "C" void kernel_launch(void* const* d_in, const int* in_sizes, int n_in,
                              void* d_out, int out_size) {
    const float* node_feats = (const float*)d_in[0];
    const float* edge_feats = (const float*)d_in[1];
    const int*   src        = (const int*)d_in[2];
    const int*   dst        = (const int*)d_in[3];
    const float* Wq  = (const float*)d_in[4];
    const float* Wk  = (const float*)d_in[5];
    const float* Wv  = (const float*)d_in[6];
    const float* We  = (const float*)d_in[7];
    const float* Wn1 = (const float*)d_in[8];
    const float* Wn2 = (const float*)d_in[9];
    const float* We1 = (const float*)d_in[10];
    const float* We2 = (const float*)d_in[11];

    float* node_out = (float*)d_out;
    float* edge_out = (float*)d_out + (size_t)NN * DD;

    float *pWqkv, *pQKV, *pWV, *pZ, *pH, *pHidN, *pScore, *pHidE;
    cudaGetSymbolAddress((void**)&pWqkv,  g_Wqkv);
    cudaGetSymbolAddress((void**)&pQKV,   g_QKV);
    cudaGetSymbolAddress((void**)&pWV,    g_wV);
    cudaGetSymbolAddress((void**)&pZ,     g_z);
    cudaGetSymbolAddress((void**)&pH,     g_h);
    cudaGetSymbolAddress((void**)&pHidN,  g_hid_n);
    cudaGetSymbolAddress((void**)&pScore, g_score);
    cudaGetSymbolAddress((void**)&pHidE,  g_hid_e);

    // 0) zero accumulators + pack weights (every replay; all capturable)
    cudaMemsetAsync(pWV, 0, (size_t)NN * DD * sizeof(float));
    cudaMemsetAsync(pZ,  0, (size_t)NN * HH * sizeof(float));
    pack_qkv_weights<<<(3 * DD * DD / 4 + 255) / 256, 256>>>(Wq, Wk, Wv);

    // 1) QKV projection in one GEMM: [N,128] x [384,128]^T -> [N,384]
    {
        dim3 grid((NN + 127) / 128, (3 * DD) / 64);
        mma_gemm_nt<0><<<grid, 256>>>(node_feats, pWqkv, pQKV, NN, 3 * DD, DD);
    }

    // 2) proj_e = edge_feats @ We^T : [E,128]
    {
        dim3 grid((EE + 127) / 128, DD / 64);
        mma_gemm_nt<0><<<grid, 256>>>(edge_feats, We, pScore, EE, DD, DD);
    }

    // 3) per-edge attention + scatter (8 warps/block, 1 edge/warp)
    edge_attn_kernel<<<(EE + 7) / 8, 256>>>(src, dst, pScore);

    // 4) h = wV / (z + eps)
    divide_kernel<<<(NN * DD / 4 + 255) / 256, 256>>>();

    // 5) node MLP: silu(h @ Wn1^T) @ Wn2^T
    {
        dim3 g1((NN + 127) / 128, (2 * DD) / 64);
        mma_gemm_nt<1><<<g1, 256>>>(pH, Wn1, pHidN, NN, 2 * DD, DD);
        dim3 g2((NN + 127) / 128, DD / 64);
        mma_gemm_nt<0><<<g2, 256>>>(pHidN, Wn2, node_out, NN, DD, 2 * DD);
    }

    // 6) edge MLP: silu(score @ We1^T) @ We2^T
    {
        dim3 g1((EE + 127) / 128, (2 * DD) / 64);
        mma_gemm_nt<1><<<g1, 256>>>(pScore, We1, pHidE, EE, 2 * DD, DD);
        dim3 g2((EE + 127) / 128, DD / 64);
        mma_gemm_nt<0><<<g2, 256>>>(pHidE, We2, edge_out, EE, DD, 2 * DD);
    }
}

// round 11
// speedup vs baseline: 1.6106x; 1.0712x over previous
#include <cuda_runtime.h>
#include <cuda_bf16.h>
#include <math.h>
#include <stdint.h>

// Problem constants (fixed by the reference)
#define NN 50000
#define EE 600000
#define DD 128
#define HH 4
#define INV_SCALE 0.17677669529663687f  // 1/sqrt(32)

// ---------------------------------------------------------------------------
// Scratch (device globals — no allocations allowed)
// ---------------------------------------------------------------------------
__device__ float g_Wqkv[3 * DD * DD];             // packed [384,128] weights
__device__ float g_QKV[(size_t)NN * 3 * DD];      // per node: [Q(128) K(128) V(128)]
__device__ float g_wV[NN * DD];
__device__ float g_z[NN * HH];
__device__ float g_h[NN * DD];
__device__ float g_hid_n[NN * 2 * DD];
__device__ float g_score[(size_t)EE * DD];        // proj_e, then score (in-place)
__device__ float g_hid_e[(size_t)EE * 2 * DD];

__device__ __forceinline__ float silu_fast(float x) {
    return __fdividef(x, 1.0f + __expf(-x));
}

// hi/lo split helpers: x = hi + lo with hi = bf16(x)
__device__ __forceinline__ uint32_t pack_hi(float x0, float x1) {
    __nv_bfloat162 r = __floats2bfloat162_rn(x0, x1);
    return *(uint32_t*)&r;
}
__device__ __forceinline__ uint32_t pack_lo(float x0, float x1) {
    float h0 = __bfloat162float(__float2bfloat16(x0));
    float h1 = __bfloat162float(__float2bfloat16(x1));
    __nv_bfloat162 r = __floats2bfloat162_rn(x0 - h0, x1 - h1);
    return *(uint32_t*)&r;
}

// ---------------------------------------------------------------------------
// Pack Wq|Wk|Wv into one [384,128] matrix
// ---------------------------------------------------------------------------
__global__ void pack_qkv_weights(const float* __restrict__ Wq,
                                 const float* __restrict__ Wk,
                                 const float* __restrict__ Wv) {
    int i = blockIdx.x * blockDim.x + threadIdx.x;
    if (i >= 3 * DD * DD / 4) return;
    const int per = DD * DD / 4;
    float4 v;
    if (i < per)            v = ((const float4*)Wq)[i];
    else if (i < 2 * per)   v = ((const float4*)Wk)[i - per];
    else                    v = ((const float4*)Wv)[i - 2 * per];
    ((float4*)g_Wqkv)[i] = v;
}

// ---------------------------------------------------------------------------
// Split-bf16 tensor-core GEMM:  C[m,n] = act( sum_k A[m,k] * W[n,k] )
//   (C = A @ W^T).  A:[M,K] row-major, W:[N,K] row-major.
//   fp32 operands split into bf16 hi+lo at tile load; 3 MMAs per product
//   (hi*hi + hi*lo + lo*hi) accumulate in fp32 -> rel err ~1e-5.
//   BM=128, BN=64, BK=32, 256 threads (8 warps), warp tile 32x32.
//   Register prefetch: next tile's LDGs are issued BEFORE the MMA section,
//   so ~600cyc of global latency overlaps the tensor-core work.
//   Requires: N % 64 == 0, K % 32 == 0.
// ---------------------------------------------------------------------------
#define MMA16816(acc, a0, a1, a2, a3, b0, b1)                               \
    asm("mma.sync.aligned.m16n8k16.row.col.f32.bf16.bf16.f32 "              \
        "{%0,%1,%2,%3}, {%4,%5,%6,%7}, {%8,%9}, {%0,%1,%2,%3};"             \
        : "+f"(acc[0]), "+f"(acc[1]), "+f"(acc[2]), "+f"(acc[3])            \
        : "r"(a0), "r"(a1), "r"(a2), "r"(a3), "r"(b0), "r"(b1))

template <int ACT>
__global__ void __launch_bounds__(256, 2)
mma_gemm_nt(const float* __restrict__ A, const float* __restrict__ W,
            float* __restrict__ C, int M, int N, int K) {
    constexpr int BM = 128, BN = 64, BK = 32;
    constexpr int LDT = 40;   // padded row stride in bf16 (conflict-free frag reads)

    __shared__ __nv_bfloat16 Ah[BM][LDT];
    __shared__ __nv_bfloat16 Al[BM][LDT];
    __shared__ __nv_bfloat16 Bh[BN][LDT];
    __shared__ __nv_bfloat16 Bl[BN][LDT];

    const int t    = threadIdx.x;
    const int lane = t & 31;
    const int warp = t >> 5;
    const int wm   = (warp >> 1) * 32;    // 0,32,64,96
    const int wn   = (warp & 1) * 32;     // 0,32
    const int g    = lane >> 2;           // 0..7
    const int tig  = lane & 3;            // 0..3

    const int m0 = blockIdx.x * BM;
    const int n0 = blockIdx.y * BN;

    // A loader mapping: thread -> (row = t>>1, kbase = (t&1)*16), 4 float4s
    const int ar = t >> 1;
    const int ak = (t & 1) * 16;
    // B loader mapping: thread -> (row = t>>2, kbase = (t&3)*8), 2 float4s
    const int br = t >> 2;
    const int bk = (t & 3) * 8;

    const int   a_gm    = m0 + ar;
    const bool  a_valid = (a_gm < M);
    const float* a_src  = A + (size_t)a_gm * K + ak;   // + k0 + i*4
    const float* b_src  = W + (size_t)(n0 + br) * K + bk;

    float acc[2][4][4];
    #pragma unroll
    for (int mi = 0; mi < 2; mi++)
        #pragma unroll
        for (int ni = 0; ni < 4; ni++)
            #pragma unroll
            for (int r = 0; r < 4; r++) acc[mi][ni][r] = 0.f;

    // ---- prologue: fetch tile 0 into registers ----
    float4 av[4], bv[2];
    #pragma unroll
    for (int i = 0; i < 4; i++) {
        av[i] = make_float4(0.f, 0.f, 0.f, 0.f);
        if (a_valid) av[i] = *(const float4*)(a_src + i * 4);
    }
    #pragma unroll
    for (int i = 0; i < 2; i++)
        bv[i] = *(const float4*)(b_src + i * 4);

    for (int k0 = 0; k0 < K; k0 += BK) {
        // ---- split + store the staged tile ----
        #pragma unroll
        for (int i = 0; i < 4; i++) {
            int kk = ak + i * 4;
            *(uint32_t*)&Ah[ar][kk + 0] = pack_hi(av[i].x, av[i].y);
            *(uint32_t*)&Ah[ar][kk + 2] = pack_hi(av[i].z, av[i].w);
            *(uint32_t*)&Al[ar][kk + 0] = pack_lo(av[i].x, av[i].y);
            *(uint32_t*)&Al[ar][kk + 2] = pack_lo(av[i].z, av[i].w);
        }
        #pragma unroll
        for (int i = 0; i < 2; i++) {
            int kk = bk + i * 4;
            *(uint32_t*)&Bh[br][kk + 0] = pack_hi(bv[i].x, bv[i].y);
            *(uint32_t*)&Bh[br][kk + 2] = pack_hi(bv[i].z, bv[i].w);
            *(uint32_t*)&Bl[br][kk + 0] = pack_lo(bv[i].x, bv[i].y);
            *(uint32_t*)&Bl[br][kk + 2] = pack_lo(bv[i].z, bv[i].w);
        }
        __syncthreads();

        // ---- prefetch NEXT tile (LDGs in flight during the MMA section) ----
        const int kn = k0 + BK;
        if (kn < K) {
            #pragma unroll
            for (int i = 0; i < 4; i++) {
                av[i] = make_float4(0.f, 0.f, 0.f, 0.f);
                if (a_valid) av[i] = *(const float4*)(a_src + kn + i * 4);
            }
            #pragma unroll
            for (int i = 0; i < 2; i++)
                bv[i] = *(const float4*)(b_src + kn + i * 4);
        }

        // ---- MMA section ----
        #pragma unroll
        for (int ka = 0; ka < 2; ka++) {
            const int kb = ka * 16;
            uint32_t fah[2][4], fal[2][4];
            #pragma unroll
            for (int mi = 0; mi < 2; mi++) {
                int r0 = wm + mi * 16 + g;
                int c0 = kb + tig * 2;
                fah[mi][0] = *(const uint32_t*)&Ah[r0][c0];
                fah[mi][1] = *(const uint32_t*)&Ah[r0 + 8][c0];
                fah[mi][2] = *(const uint32_t*)&Ah[r0][c0 + 8];
                fah[mi][3] = *(const uint32_t*)&Ah[r0 + 8][c0 + 8];
                fal[mi][0] = *(const uint32_t*)&Al[r0][c0];
                fal[mi][1] = *(const uint32_t*)&Al[r0 + 8][c0];
                fal[mi][2] = *(const uint32_t*)&Al[r0][c0 + 8];
                fal[mi][3] = *(const uint32_t*)&Al[r0 + 8][c0 + 8];
            }
            #pragma unroll
            for (int ni = 0; ni < 4; ni++) {
                int nrow = wn + ni * 8 + g;
                int c0 = kb + tig * 2;
                uint32_t bh0 = *(const uint32_t*)&Bh[nrow][c0];
                uint32_t bh1 = *(const uint32_t*)&Bh[nrow][c0 + 8];
                uint32_t bl0 = *(const uint32_t*)&Bl[nrow][c0];
                uint32_t bl1 = *(const uint32_t*)&Bl[nrow][c0 + 8];
                #pragma unroll
                for (int mi = 0; mi < 2; mi++) {
                    MMA16816(acc[mi][ni], fah[mi][0], fah[mi][1], fah[mi][2], fah[mi][3], bh0, bh1);
                    MMA16816(acc[mi][ni], fah[mi][0], fah[mi][1], fah[mi][2], fah[mi][3], bl0, bl1);
                    MMA16816(acc[mi][ni], fal[mi][0], fal[mi][1], fal[mi][2], fal[mi][3], bh0, bh1);
                }
            }
        }
        __syncthreads();
    }

    // ---- epilogue ----
    #pragma unroll
    for (int mi = 0; mi < 2; mi++) {
        #pragma unroll
        for (int ni = 0; ni < 4; ni++) {
            int gm0 = m0 + wm + mi * 16 + g;
            int col = n0 + wn + ni * 8 + tig * 2;
            float d0 = acc[mi][ni][0], d1 = acc[mi][ni][1];
            float d2 = acc[mi][ni][2], d3 = acc[mi][ni][3];
            if (ACT == 1) {
                d0 = silu_fast(d0); d1 = silu_fast(d1);
                d2 = silu_fast(d2); d3 = silu_fast(d3);
            }
            if (gm0 < M)
                *(float2*)(C + (size_t)gm0 * N + col) = make_float2(d0, d1);
            if (gm0 + 8 < M)
                *(float2*)(C + (size_t)(gm0 + 8) * N + col) = make_float2(d2, d3);
        }
    }
}

// ---------------------------------------------------------------------------
// Per-edge attention: one WARP per edge, lane handles 4 contiguous floats.
//   QKV packed per node: row stride 384 floats [Q | K | V]
// ---------------------------------------------------------------------------
__global__ void __launch_bounds__(256)
edge_attn_kernel(const int* __restrict__ src, const int* __restrict__ dst,
                 float* __restrict__ score) {
    const int warp = threadIdx.x >> 5;
    const int lane = threadIdx.x & 31;
    const int e = blockIdx.x * 8 + warp;
    if (e >= EE) return;

    const int sn = __ldg(src + e);
    const int dn = __ldg(dst + e);
    const int base = lane * 4;              // 0..124; head = lane>>3

    const float* srow = g_QKV + (size_t)sn * (3 * DD);
    const float* drow = g_QKV + (size_t)dn * (3 * DD);

    float4 q4 = *(const float4*)(drow + base);              // Q[dst]
    float4 k4 = *(const float4*)(srow + DD + base);         // K[src]
    float4 p4 = *(const float4*)(score + (size_t)e * DD + base);

    float4 sc;
    sc.x = fminf(5.f, fmaxf(-5.f, k4.x * q4.x * INV_SCALE)) * p4.x;
    sc.y = fminf(5.f, fmaxf(-5.f, k4.y * q4.y * INV_SCALE)) * p4.y;
    sc.z = fminf(5.f, fmaxf(-5.f, k4.z * q4.z * INV_SCALE)) * p4.z;
    sc.w = fminf(5.f, fmaxf(-5.f, k4.w * q4.w * INV_SCALE)) * p4.w;
    *(float4*)(score + (size_t)e * DD + base) = sc;

    // reduce 32 values per head: 4 in-thread + butterfly over the 8-lane group
    float sum = (sc.x + sc.y) + (sc.z + sc.w);
    #pragma unroll
    for (int off = 4; off > 0; off >>= 1)
        sum += __shfl_xor_sync(0xffffffffu, sum, off);

    float s = __expf(fminf(5.f, fmaxf(-5.f, sum)));

    float4 v4 = *(const float4*)(srow + 2 * DD + base);     // V[src]
    float4* wv = (float4*)(g_wV + (size_t)dn * DD + base);
    atomicAdd(wv, make_float4(v4.x * s, v4.y * s, v4.z * s, v4.w * s));
    if ((lane & 7) == 0) atomicAdd(&g_z[dn * HH + (lane >> 3)], s);
}

// ---------------------------------------------------------------------------
// h = wV / (z + 1e-6), float4-wide
// ---------------------------------------------------------------------------
__global__ void divide_kernel() {
    int idx = blockIdx.x * blockDim.x + threadIdx.x;   // one float4 per thread
    if (idx >= NN * DD / 4) return;
    int fbase = idx * 4;
    int n = fbase >> 7;
    int head = (fbase & 127) >> 5;
    float inv = __fdividef(1.0f, g_z[n * HH + head] + 1e-6f);
    float4 w = *(const float4*)(g_wV + fbase);
    w.x *= inv; w.y *= inv; w.z *= inv; w.w *= inv;
    *(float4*)(g_h + fbase) = w;
}

// ---------------------------------------------------------------------------
// kernel_launch
// inputs: 0 node_feats 1 edge_feats 2 src 3 dst 4 Wq 5 Wk 6 Wv 7 We
//         8 Wn1 9 Wn2 10 We1 11 We2
// output: [node_out (N*128) | edge_out (E*128)] fp32
// ---------------------------------------------------------------------------
extern "C" void kernel_launch(void* const* d_in, const int* in_sizes, int n_in,
                              void* d_out, int out_size) {
    const float* node_feats = (const float*)d_in[0];
    const float* edge_feats = (const float*)d_in[1];
    const int*   src        = (const int*)d_in[2];
    const int*   dst        = (const int*)d_in[3];
    const float* Wq  = (const float*)d_in[4];
    const float* Wk  = (const float*)d_in[5];
    const float* Wv  = (const float*)d_in[6];
    const float* We  = (const float*)d_in[7];
    const float* Wn1 = (const float*)d_in[8];
    const float* Wn2 = (const float*)d_in[9];
    const float* We1 = (const float*)d_in[10];
    const float* We2 = (const float*)d_in[11];

    float* node_out = (float*)d_out;
    float* edge_out = (float*)d_out + (size_t)NN * DD;

    float *pWqkv, *pQKV, *pWV, *pZ, *pH, *pHidN, *pScore, *pHidE;
    cudaGetSymbolAddress((void**)&pWqkv,  g_Wqkv);
    cudaGetSymbolAddress((void**)&pQKV,   g_QKV);
    cudaGetSymbolAddress((void**)&pWV,    g_wV);
    cudaGetSymbolAddress((void**)&pZ,     g_z);
    cudaGetSymbolAddress((void**)&pH,     g_h);
    cudaGetSymbolAddress((void**)&pHidN,  g_hid_n);
    cudaGetSymbolAddress((void**)&pScore, g_score);
    cudaGetSymbolAddress((void**)&pHidE,  g_hid_e);

    // 0) zero accumulators + pack weights (every replay; all capturable)
    cudaMemsetAsync(pWV, 0, (size_t)NN * DD * sizeof(float));
    cudaMemsetAsync(pZ,  0, (size_t)NN * HH * sizeof(float));
    pack_qkv_weights<<<(3 * DD * DD / 4 + 255) / 256, 256>>>(Wq, Wk, Wv);

    // 1) QKV projection in one GEMM: [N,128] x [384,128]^T -> [N,384]
    {
        dim3 grid((NN + 127) / 128, (3 * DD) / 64);
        mma_gemm_nt<0><<<grid, 256>>>(node_feats, pWqkv, pQKV, NN, 3 * DD, DD);
    }

    // 2) proj_e = edge_feats @ We^T : [E,128]
    {
        dim3 grid((EE + 127) / 128, DD / 64);
        mma_gemm_nt<0><<<grid, 256>>>(edge_feats, We, pScore, EE, DD, DD);
    }

    // 3) per-edge attention + scatter (8 warps/block, 1 edge/warp)
    edge_attn_kernel<<<(EE + 7) / 8, 256>>>(src, dst, pScore);

    // 4) h = wV / (z + eps)
    divide_kernel<<<(NN * DD / 4 + 255) / 256, 256>>>();

    // 5) node MLP: silu(h @ Wn1^T) @ Wn2^T
    {
        dim3 g1((NN + 127) / 128, (2 * DD) / 64);
        mma_gemm_nt<1><<<g1, 256>>>(pH, Wn1, pHidN, NN, 2 * DD, DD);
        dim3 g2((NN + 127) / 128, DD / 64);
        mma_gemm_nt<0><<<g2, 256>>>(pHidN, Wn2, node_out, NN, DD, 2 * DD);
    }

    // 6) edge MLP: silu(score @ We1^T) @ We2^T
    {
        dim3 g1((EE + 127) / 128, (2 * DD) / 64);
        mma_gemm_nt<1><<<g1, 256>>>(pScore, We1, pHidE, EE, 2 * DD, DD);
        dim3 g2((EE + 127) / 128, DD / 64);
        mma_gemm_nt<0><<<g2, 256>>>(pHidE, We2, edge_out, EE, DD, 2 * DD);
    }
}